// round 12
// baseline (speedup 1.0000x reference)
#include <cuda_runtime.h>
#include <cuda_bf16.h>
#include <cstddef>
#include <cstdint>

#define TSTEPS 1024
#define BATCH  64
#define DIN    256
#define DHID   256
#define NC     1024
#define M_TOTAL (TSTEPS * BATCH)
#define KTOT   768            // split-bf16 virtual K: [Xhi|Xhi|Xlo] x [Whi;Wlo;Whi]

#define CLUSTER 8
#define NCTA    128
#define RTHR    1024          // 32 warps = 32 hidden units per CTA

// packed column: pc = part*128 + u*4 + gate, j = part*32 + u, gate in {f,i,g,o}

__device__ float         g_xp[(size_t)M_TOTAL * NC];     // x-proj + bias [m][pc]
__device__ __nv_bfloat16 g_Ax[(size_t)M_TOTAL * KTOT];   // split-bf16 A' [m][k']
__device__ __nv_bfloat16 g_Bx[(size_t)NC * KTOT];        // split-bf16 B' [pc][k']
__device__ float         g_Whp2[DHID * NC];              // Wh [part][i32][c128][kc8]
__device__ float         g_bp[NC];

// ============================ helpers ============================
__device__ __forceinline__ uint32_t smem_u32(const void* p) {
    uint32_t a;
    asm("{ .reg .u64 t; cvta.to.shared.u64 t, %1; cvt.u32.u64 %0, t; }" : "=r"(a) : "l"(p));
    return a;
}
#define SW128(off) ((off) ^ (((off) >> 3) & 0x70))

__device__ __forceinline__ void ldsm4(uint32_t* r, uint32_t addr) {
    asm volatile("ldmatrix.sync.aligned.m8n8.x4.shared.b16 {%0,%1,%2,%3}, [%4];"
                 : "=r"(r[0]), "=r"(r[1]), "=r"(r[2]), "=r"(r[3]) : "r"(addr));
}
__device__ __forceinline__ void mma16816(float* c, const uint32_t* a, uint32_t b0, uint32_t b1) {
    asm volatile("mma.sync.aligned.m16n8k16.row.col.f32.bf16.bf16.f32 "
                 "{%0,%1,%2,%3}, {%4,%5,%6,%7}, {%8,%9}, {%0,%1,%2,%3};"
                 : "+f"(c[0]), "+f"(c[1]), "+f"(c[2]), "+f"(c[3])
                 : "r"(a[0]), "r"(a[1]), "r"(a[2]), "r"(a[3]), "r"(b0), "r"(b1));
}

// ============================ pack kernels ============================
__global__ void packB_kernel(const float* __restrict__ Wf, const float* __restrict__ bf,
                             const float* __restrict__ Wi, const float* __restrict__ bi,
                             const float* __restrict__ Wg, const float* __restrict__ bg,
                             const float* __restrict__ Wo, const float* __restrict__ bo)
{
    int idx = blockIdx.x * blockDim.x + threadIdx.x;
    if (idx >= DIN * NC) return;
    int k    = idx >> 10;
    int pc   = idx & (NC - 1);
    int part = pc >> 7;
    int c    = pc & 127;
    int u    = c >> 2;
    int gate = c & 3;
    int j    = part * 32 + u;
    const float* W = (gate == 0) ? Wf : (gate == 1) ? Wi : (gate == 2) ? Wg : Wo;
    const float* b = (gate == 0) ? bf : (gate == 1) ? bi : (gate == 2) ? bg : bo;

    float wx = W[(size_t)k * DHID + j];
    __nv_bfloat16 hi = __float2bfloat16_rn(wx);
    float lo = wx - __bfloat162float(hi);
    g_Bx[(size_t)pc * KTOT + k]       = hi;                        // pairs with Xhi
    g_Bx[(size_t)pc * KTOT + 256 + k] = __float2bfloat16_rn(lo);   // pairs with Xhi
    g_Bx[(size_t)pc * KTOT + 512 + k] = hi;                        // pairs with Xlo

    // recur weight layout: [part][i][c][kc], k = kc*32 + i  (conflict-free LDS.32)
    float wh = W[(size_t)(DIN + k) * DHID + j];
    int kc = k >> 5, i = k & 31;
    g_Whp2[(size_t)part * 32768 + ((i * 128 + c) * 8) + kc] = wh;
    if (k == 0) g_bp[pc] = b[j];
}

__global__ void packA_kernel(const float* __restrict__ X)
{
    int idx = blockIdx.x * blockDim.x + threadIdx.x;
    if (idx >= M_TOTAL * (DIN / 4)) return;
    int m  = idx >> 6;
    int kq = idx & 63;
    float4 v = *(const float4*)&X[(size_t)m * DIN + kq * 4];
    __nv_bfloat162 h0 = __floats2bfloat162_rn(v.x, v.y);
    __nv_bfloat162 h1 = __floats2bfloat162_rn(v.z, v.w);
    float lx = v.x - __bfloat162float(h0.x);
    float ly = v.y - __bfloat162float(h0.y);
    float lz = v.z - __bfloat162float(h1.x);
    float lw = v.w - __bfloat162float(h1.y);
    __nv_bfloat162 l0 = __floats2bfloat162_rn(lx, ly);
    __nv_bfloat162 l1 = __floats2bfloat162_rn(lz, lw);
    size_t base = (size_t)m * KTOT + kq * 4;
    *(__nv_bfloat162*)&g_Ax[base]       = h0;
    *(__nv_bfloat162*)&g_Ax[base + 2]   = h1;
    *(__nv_bfloat162*)&g_Ax[base + 256] = h0;
    *(__nv_bfloat162*)&g_Ax[base + 258] = h1;
    *(__nv_bfloat162*)&g_Ax[base + 512] = l0;
    *(__nv_bfloat162*)&g_Ax[base + 514] = l1;
}

// ============================ xproj GEMM: mma.sync bf16 (proven) ============================
#define XT 256
#define BK 64
#define NCHUNK (KTOT / BK)

__global__ __launch_bounds__(XT) void xproj_mma()
{
    __shared__ __align__(128) __nv_bfloat16 sAbuf[128 * 64];
    __shared__ __align__(128) __nv_bfloat16 sBbuf[128 * 64];

    const int tid    = threadIdx.x;
    const int wid    = tid >> 5;
    const int lane   = tid & 31;
    const int warp_m = wid >> 2;
    const int warp_n = wid & 3;
    const int n0     = blockIdx.x * 128;
    const int m0     = blockIdx.y * 128;

    const uint32_t sA32 = smem_u32(sAbuf);
    const uint32_t sB32 = smem_u32(sBbuf);
    char* sAp = (char*)sAbuf;
    char* sBp = (char*)sBbuf;

    const int g  = lane >> 3;
    const int lr = lane & 7;
    const int rA   = warp_m * 64 + (g & 1) * 8 + lr;
    const int hbA  = (g >> 1) * 16;
    const int rB   = warp_n * 32 + (g >> 1) * 8 + lr;
    const int hbB  = (g & 1) * 16;

    float acc[4][4][4];
    #pragma unroll
    for (int i = 0; i < 4; i++)
        #pragma unroll
        for (int jj = 0; jj < 4; jj++)
            #pragma unroll
            for (int q = 0; q < 4; q++) acc[i][jj][q] = 0.0f;

    uint4 rAv[4], rBv[4];
    #pragma unroll
    for (int i = 0; i < 4; i++) {
        int idx = tid + i * 256, row = idx >> 3, q = idx & 7;
        rAv[i] = *(const uint4*)&g_Ax[(size_t)(m0 + row) * KTOT + q * 8];
        rBv[i] = *(const uint4*)&g_Bx[(size_t)(n0 + row) * KTOT + q * 8];
    }

    for (int c = 0; c < NCHUNK; c++) {
        #pragma unroll
        for (int i = 0; i < 4; i++) {
            int idx = tid + i * 256, row = idx >> 3, q = idx & 7;
            *(uint4*)(sAp + SW128(row * 128 + q * 16)) = rAv[i];
            *(uint4*)(sBp + SW128(row * 128 + q * 16)) = rBv[i];
        }
        __syncthreads();

        if (c + 1 < NCHUNK) {
            #pragma unroll
            for (int i = 0; i < 4; i++) {
                int idx = tid + i * 256, row = idx >> 3, q = idx & 7;
                rAv[i] = *(const uint4*)&g_Ax[(size_t)(m0 + row) * KTOT + (c + 1) * BK + q * 8];
                rBv[i] = *(const uint4*)&g_Bx[(size_t)(n0 + row) * KTOT + (c + 1) * BK + q * 8];
            }
        }

        #pragma unroll
        for (int kk = 0; kk < 4; kk++) {
            uint32_t a[4][4], b[2][4];
            #pragma unroll
            for (int mt = 0; mt < 4; mt++) {
                int row = rA + mt * 16;
                ldsm4(a[mt], sA32 + row * 128 + ((kk * 32 + hbA) ^ ((row << 4) & 0x70)));
            }
            #pragma unroll
            for (int h = 0; h < 2; h++) {
                int row = rB + h * 16;
                ldsm4(b[h], sB32 + row * 128 + ((kk * 32 + hbB) ^ ((row << 4) & 0x70)));
            }
            #pragma unroll
            for (int mt = 0; mt < 4; mt++)
                #pragma unroll
                for (int nt = 0; nt < 4; nt++)
                    mma16816(acc[mt][nt], a[mt], b[nt >> 1][(nt & 1) * 2], b[nt >> 1][(nt & 1) * 2 + 1]);
        }
        __syncthreads();
    }

    const int er = lane >> 2;
    const int ec = (lane & 3) * 2;
    #pragma unroll
    for (int mt = 0; mt < 4; mt++) {
        int m = m0 + warp_m * 64 + mt * 16 + er;
        #pragma unroll
        for (int nt = 0; nt < 4; nt++) {
            int n = n0 + warp_n * 32 + nt * 8 + ec;
            float2 bias = *(const float2*)&g_bp[n];
            float2 o0 = make_float2(acc[mt][nt][0] + bias.x, acc[mt][nt][1] + bias.y);
            float2 o1 = make_float2(acc[mt][nt][2] + bias.x, acc[mt][nt][3] + bias.y);
            *(float2*)&g_xp[(size_t)m * NC + n]       = o0;
            *(float2*)&g_xp[(size_t)(m + 8) * NC + n] = o1;
        }
    }
}

// ============================ recurrent kernel: warp-autonomous steps ============================
// 16 clusters of 8 CTAs. Warp wid owns hidden unit j = part*32 + wid.
// Lane = (cg = gate octet 0..3) x (kc = k-chunk 0..7): partial dot for col c = wid*4+cg over
// k = kc*32..+31, all 4 batches (fma2 pairs). kc-reduction = shfl.bfly in-warp; gate transpose
// via 16-float per-warp smem + syncwarp; lanes 0..3 update (c,h); broadcast = ONE remote store
// per lane (lane = peer*4 + b). Only cross-warp sync: barrier.cluster once per step (R8-proven).
__global__ void __cluster_dims__(CLUSTER, 1, 1) __launch_bounds__(RTHR, 1)
recur_kernel(float* __restrict__ out)
{
    extern __shared__ float sm[];
    float* ws  = sm;                  // weights [i32][c128][kc8]  = 32768 floats (128 KB)
    float* hb  = sm + 32768;          // h [2][i32][kc8][b4]       =  2048 floats (8 KB)
    float* act = sm + 32768 + 2048;   // per-warp [g4][b4]          =   512 floats (2 KB)

    const int tid  = threadIdx.x;
    const int part = blockIdx.x & (CLUSTER - 1);
    const int grp  = blockIdx.x >> 3;
    const int wid  = tid >> 5;
    const int lane = tid & 31;
    const int kc   = lane & 7;        // k-chunk
    const int cg   = lane >> 3;       // gate octet 0..3
    const int bl   = lane & 3;        // combine batch (lanes 0..3)
    const int j    = part * 32 + wid; // this warp's hidden unit

    // load this part's weights into smem (coalesced), zero h buffers
    for (int idx = tid; idx < 32768; idx += RTHR)
        ws[idx] = g_Whp2[(size_t)part * 32768 + idx];
    for (int idx = tid; idx < 2048; idx += RTHR) hb[idx] = 0.0f;
    __syncthreads();
    asm volatile("barrier.cluster.arrive.aligned;" ::: "memory");
    asm volatile("barrier.cluster.wait.aligned;" ::: "memory");

    const uint32_t hb32 = smem_u32(hb);
    const float* wsp = ws + (wid * 4 + cg) * 8 + kc;   // ws[(i*128 + c)*8 + kc], step i: +1024

    // remote-store identity: lane = peer*4 + b
    const int peer = lane >> 2;
    const unsigned hoff_st = (unsigned)(((j & 31) * 8 + (j >> 5)) * 4 + bl) * 4u;

    float cstate = 0.0f;
    float hlast  = 0.0f;

    for (int t = 0; t < TSTEPS; t++) {
        const int p = t & 1;

        // xp prefetch: lanes 0..15 = (b = lane>>2, g = lane&3)
        float xpv = 0.0f;
        if (lane < 16)
            xpv = g_xp[((size_t)t * BATCH + grp * 4 + (lane >> 2)) * NC
                       + part * 128 + wid * 4 + (lane & 3)];

        // ---- stage 1: partial dot over 32 k for col (wid,cg), 4 batches ----
        unsigned long long acc01 = 0ull, acc23 = 0ull;
        {
            const float* hrow = hb + p * 1024 + kc * 4;   // [(i*8+kc)*4 + b]
            #pragma unroll
            for (int i = 0; i < 32; i++) {
                ulonglong2 hh = *(const ulonglong2*)&hrow[i * 32];
                float wv = wsp[i * 1024];
                unsigned long long ww;
                asm("mov.b64 %0, {%1, %1};" : "=l"(ww) : "f"(wv));
                asm("fma.rn.f32x2 %0, %1, %2, %0;" : "+l"(acc01) : "l"(ww), "l"(hh.x));
                asm("fma.rn.f32x2 %0, %1, %2, %0;" : "+l"(acc23) : "l"(ww), "l"(hh.y));
            }
        }
        float s0, s1, s2, s3;
        asm("mov.b64 {%0, %1}, %2;" : "=f"(s0), "=f"(s1) : "l"(acc01));
        asm("mov.b64 {%0, %1}, %2;" : "=f"(s2), "=f"(s3) : "l"(acc23));

        // ---- kc reduction: butterfly within each octet ----
        #pragma unroll
        for (int m = 1; m < 8; m <<= 1) {
            s0 += __shfl_xor_sync(0xffffffffu, s0, m);
            s1 += __shfl_xor_sync(0xffffffffu, s1, m);
            s2 += __shfl_xor_sync(0xffffffffu, s2, m);
            s3 += __shfl_xor_sync(0xffffffffu, s3, m);
        }
        // add x-projection (gather per batch from prefetch lanes b*4+cg)
        s0 += __shfl_sync(0xffffffffu, xpv, 0 * 4 + cg);
        s1 += __shfl_sync(0xffffffffu, xpv, 1 * 4 + cg);
        s2 += __shfl_sync(0xffffffffu, xpv, 2 * 4 + cg);
        s3 += __shfl_sync(0xffffffffu, xpv, 3 * 4 + cg);

        // ---- gate activation (octet-redundant; cg = gate) ----
        float r0, r1, r2, r3;
        if (cg == 2) {
            asm("tanh.approx.f32 %0, %1;" : "=f"(r0) : "f"(s0));
            asm("tanh.approx.f32 %0, %1;" : "=f"(r1) : "f"(s1));
            asm("tanh.approx.f32 %0, %1;" : "=f"(r2) : "f"(s2));
            asm("tanh.approx.f32 %0, %1;" : "=f"(r3) : "f"(s3));
        } else {
            r0 = 1.0f / (1.0f + __expf(-s0));
            r1 = 1.0f / (1.0f + __expf(-s1));
            r2 = 1.0f / (1.0f + __expf(-s2));
            r3 = 1.0f / (1.0f + __expf(-s3));
        }
        if (kc == 0)
            *(float4*)&act[wid * 16 + cg * 4] = make_float4(r0, r1, r2, r3);
        __syncwarp();

        // ---- combine (lanes 0..3): batch bl, unit j ----
        float h = 0.0f;
        if (lane < 4) {
            float fv = act[wid * 16 + 0 + bl];
            float iv = act[wid * 16 + 4 + bl];
            float gv = act[wid * 16 + 8 + bl];
            float ov = act[wid * 16 + 12 + bl];
            float ct;
            cstate = fv * cstate + iv * gv;
            asm("tanh.approx.f32 %0, %1;" : "=f"(ct) : "f"(cstate));
            h = ov * ct;
            hlast = h;
            out[(size_t)t * (BATCH * DHID) + (size_t)(grp * 4 + bl) * DHID + j] = h;
        }

        // ---- broadcast: one remote store per lane (peer = lane>>2, b = lane&3) ----
        float hh = __shfl_sync(0xffffffffu, h, bl);
        {
            unsigned dst = hb32 + (unsigned)((1 - p) * 1024) * 4u + hoff_st;
            unsigned rem;
            asm("mapa.shared::cluster.u32 %0, %1, %2;" : "=r"(rem) : "r"(dst), "r"((unsigned)peer));
            asm volatile("st.shared::cluster.f32 [%0], %1;" :: "r"(rem), "f"(hh) : "memory");
        }

        // ---- step barrier (R8-proven ordering) ----
        asm volatile("barrier.cluster.arrive.aligned;" ::: "memory");
        asm volatile("barrier.cluster.wait.aligned;" ::: "memory");
    }

    if (tid % 32 < 4) {
        const size_t HT_OFF = (size_t)TSTEPS * BATCH * DHID;
        out[HT_OFF + (size_t)(grp * 4 + bl) * DHID + j] = hlast;
        out[HT_OFF + (size_t)BATCH * DHID + (size_t)(grp * 4 + bl) * DHID + j] = cstate;
    }

    asm volatile("barrier.cluster.arrive.aligned;" ::: "memory");
    asm volatile("barrier.cluster.wait.aligned;" ::: "memory");
}

// ============================ launch ============================
#define RSMEM ((32768 + 2048 + 512) * 4)

extern "C" void kernel_launch(void* const* d_in, const int* in_sizes, int n_in,
                              void* d_out, int out_size)
{
    const float* X  = (const float*)d_in[0];
    const float* Wf = (const float*)d_in[1];
    const float* bf = (const float*)d_in[2];
    const float* Wi = (const float*)d_in[3];
    const float* bi = (const float*)d_in[4];
    const float* Wg = (const float*)d_in[5];
    const float* bg = (const float*)d_in[6];
    const float* Wo = (const float*)d_in[7];
    const float* bo = (const float*)d_in[8];
    float* out = (float*)d_out;

    cudaFuncSetAttribute(recur_kernel, cudaFuncAttributeMaxDynamicSharedMemorySize, RSMEM);

    packB_kernel<<<(DIN * NC + 255) / 256, 256>>>(Wf, bf, Wi, bi, Wg, bg, Wo, bo);
    packA_kernel<<<(M_TOTAL * (DIN / 4) + 255) / 256, 256>>>(X);

    dim3 ggrid(NC / 128, M_TOTAL / 128);
    xproj_mma<<<ggrid, XT>>>();

    recur_kernel<<<NCTA, RTHR, RSMEM>>>(out);
}

// round 13
// speedup vs baseline: 1.7059x; 1.7059x over previous
#include <cuda_runtime.h>
#include <cuda_bf16.h>
#include <cstddef>
#include <cstdint>

#define TSTEPS 1024
#define BATCH  64
#define DIN    256
#define DHID   256
#define NC     1024
#define M_TOTAL (TSTEPS * BATCH)
#define KTOT   768            // split-bf16 virtual K: [Xhi|Xhi|Xlo] x [Whi;Wlo;Whi]

#define CLUSTER 8
#define NCTA    64            // 8 clusters x 8 CTAs; each cluster owns 8 batches (2 groups of 4)
#define RTHR    1024          // 32 warps: kc(8) x c(128)

// packed column: pc = part*128 + u*4 + gate, j = part*32 + u, gate in {f,i,g,o}

__device__ float         g_xp[(size_t)M_TOTAL * NC];     // x-proj + bias [m][pc]
__device__ __nv_bfloat16 g_Ax[(size_t)M_TOTAL * KTOT];   // split-bf16 A' [m][k']
__device__ __nv_bfloat16 g_Bx[(size_t)NC * KTOT];        // split-bf16 B' [pc][k']
__device__ float         g_Whp[DHID * NC];               // fp32 Wh [part][kc8][i32][c128]
__device__ float         g_bp[NC];

// ============================ helpers ============================
__device__ __forceinline__ uint32_t smem_u32(const void* p) {
    uint32_t a;
    asm("{ .reg .u64 t; cvta.to.shared.u64 t, %1; cvt.u32.u64 %0, t; }" : "=r"(a) : "l"(p));
    return a;
}
#define SW128(off) ((off) ^ (((off) >> 3) & 0x70))

__device__ __forceinline__ void ldsm4(uint32_t* r, uint32_t addr) {
    asm volatile("ldmatrix.sync.aligned.m8n8.x4.shared.b16 {%0,%1,%2,%3}, [%4];"
                 : "=r"(r[0]), "=r"(r[1]), "=r"(r[2]), "=r"(r[3]) : "r"(addr));
}
__device__ __forceinline__ void mma16816(float* c, const uint32_t* a, uint32_t b0, uint32_t b1) {
    asm volatile("mma.sync.aligned.m16n8k16.row.col.f32.bf16.bf16.f32 "
                 "{%0,%1,%2,%3}, {%4,%5,%6,%7}, {%8,%9}, {%0,%1,%2,%3};"
                 : "+f"(c[0]), "+f"(c[1]), "+f"(c[2]), "+f"(c[3])
                 : "r"(a[0]), "r"(a[1]), "r"(a[2]), "r"(a[3]), "r"(b0), "r"(b1));
}

// mbarrier wait, acquire at CLUSTER scope (pairs with producers' release fence)
#define MBAR_WAIT_CL(a, ph) do {                                                  \
    uint32_t _m = (a), _p = (ph), _d;                                             \
    asm volatile("{\n\t.reg .pred p;\n\t"                                         \
        "mbarrier.try_wait.parity.acquire.cluster.shared::cta.b64 p, [%1], %2;\n\t" \
        "selp.b32 %0, 1, 0, p;\n\t}" : "=r"(_d) : "r"(_m), "r"(_p) : "memory");   \
    if (!_d) {                                                                    \
        asm volatile("{\n\t.reg .pred P1;\n\tWL_%=:\n\t"                          \
            "mbarrier.try_wait.parity.acquire.cluster.shared::cta.b64 P1, [%0], %1, 0x989680;\n\t" \
            "@P1 bra.uni WD_%=;\n\tbra.uni WL_%=;\n\tWD_%=:\n\t}"                 \
            :: "r"(_m), "r"(_p) : "memory");                                      \
    }                                                                             \
} while (0)

// ============================ pack kernels ============================
__global__ void packB_kernel(const float* __restrict__ Wf, const float* __restrict__ bf,
                             const float* __restrict__ Wi, const float* __restrict__ bi,
                             const float* __restrict__ Wg, const float* __restrict__ bg,
                             const float* __restrict__ Wo, const float* __restrict__ bo)
{
    int idx = blockIdx.x * blockDim.x + threadIdx.x;
    if (idx >= DIN * NC) return;
    int k    = idx >> 10;
    int pc   = idx & (NC - 1);
    int part = pc >> 7;
    int c    = pc & 127;
    int u    = c >> 2;
    int gate = c & 3;
    int j    = part * 32 + u;
    const float* W = (gate == 0) ? Wf : (gate == 1) ? Wi : (gate == 2) ? Wg : Wo;
    const float* b = (gate == 0) ? bf : (gate == 1) ? bi : (gate == 2) ? bg : bo;

    float wx = W[(size_t)k * DHID + j];
    __nv_bfloat16 hi = __float2bfloat16_rn(wx);
    float lo = wx - __bfloat162float(hi);
    g_Bx[(size_t)pc * KTOT + k]       = hi;                        // pairs with Xhi
    g_Bx[(size_t)pc * KTOT + 256 + k] = __float2bfloat16_rn(lo);   // pairs with Xhi
    g_Bx[(size_t)pc * KTOT + 512 + k] = hi;                        // pairs with Xlo

    float wh = W[(size_t)(DIN + k) * DHID + j];
    int kc = k >> 5, i = k & 31;   // 8 chunks of 32 k
    g_Whp[(size_t)(((part * 8 + kc) * 32) + i) * 128 + c] = wh;
    if (k == 0) g_bp[pc] = b[j];
}

__global__ void packA_kernel(const float* __restrict__ X)
{
    int idx = blockIdx.x * blockDim.x + threadIdx.x;
    if (idx >= M_TOTAL * (DIN / 4)) return;
    int m  = idx >> 6;
    int kq = idx & 63;
    float4 v = *(const float4*)&X[(size_t)m * DIN + kq * 4];
    __nv_bfloat162 h0 = __floats2bfloat162_rn(v.x, v.y);
    __nv_bfloat162 h1 = __floats2bfloat162_rn(v.z, v.w);
    float lx = v.x - __bfloat162float(h0.x);
    float ly = v.y - __bfloat162float(h0.y);
    float lz = v.z - __bfloat162float(h1.x);
    float lw = v.w - __bfloat162float(h1.y);
    __nv_bfloat162 l0 = __floats2bfloat162_rn(lx, ly);
    __nv_bfloat162 l1 = __floats2bfloat162_rn(lz, lw);
    size_t base = (size_t)m * KTOT + kq * 4;
    *(__nv_bfloat162*)&g_Ax[base]       = h0;
    *(__nv_bfloat162*)&g_Ax[base + 2]   = h1;
    *(__nv_bfloat162*)&g_Ax[base + 256] = h0;
    *(__nv_bfloat162*)&g_Ax[base + 258] = h1;
    *(__nv_bfloat162*)&g_Ax[base + 512] = l0;
    *(__nv_bfloat162*)&g_Ax[base + 514] = l1;
}

// ============================ xproj GEMM: mma.sync bf16 (proven) ============================
#define XT 256
#define BK 64
#define NCHUNK (KTOT / BK)

__global__ __launch_bounds__(XT) void xproj_mma()
{
    __shared__ __align__(128) __nv_bfloat16 sAbuf[128 * 64];
    __shared__ __align__(128) __nv_bfloat16 sBbuf[128 * 64];

    const int tid    = threadIdx.x;
    const int wid    = tid >> 5;
    const int lane   = tid & 31;
    const int warp_m = wid >> 2;
    const int warp_n = wid & 3;
    const int n0     = blockIdx.x * 128;
    const int m0     = blockIdx.y * 128;

    const uint32_t sA32 = smem_u32(sAbuf);
    const uint32_t sB32 = smem_u32(sBbuf);
    char* sAp = (char*)sAbuf;
    char* sBp = (char*)sBbuf;

    const int g  = lane >> 3;
    const int lr = lane & 7;
    const int rA   = warp_m * 64 + (g & 1) * 8 + lr;
    const int hbA  = (g >> 1) * 16;
    const int rB   = warp_n * 32 + (g >> 1) * 8 + lr;
    const int hbB  = (g & 1) * 16;

    float acc[4][4][4];
    #pragma unroll
    for (int i = 0; i < 4; i++)
        #pragma unroll
        for (int jj = 0; jj < 4; jj++)
            #pragma unroll
            for (int q = 0; q < 4; q++) acc[i][jj][q] = 0.0f;

    uint4 rAv[4], rBv[4];
    #pragma unroll
    for (int i = 0; i < 4; i++) {
        int idx = tid + i * 256, row = idx >> 3, q = idx & 7;
        rAv[i] = *(const uint4*)&g_Ax[(size_t)(m0 + row) * KTOT + q * 8];
        rBv[i] = *(const uint4*)&g_Bx[(size_t)(n0 + row) * KTOT + q * 8];
    }

    for (int c = 0; c < NCHUNK; c++) {
        #pragma unroll
        for (int i = 0; i < 4; i++) {
            int idx = tid + i * 256, row = idx >> 3, q = idx & 7;
            *(uint4*)(sAp + SW128(row * 128 + q * 16)) = rAv[i];
            *(uint4*)(sBp + SW128(row * 128 + q * 16)) = rBv[i];
        }
        __syncthreads();

        if (c + 1 < NCHUNK) {
            #pragma unroll
            for (int i = 0; i < 4; i++) {
                int idx = tid + i * 256, row = idx >> 3, q = idx & 7;
                rAv[i] = *(const uint4*)&g_Ax[(size_t)(m0 + row) * KTOT + (c + 1) * BK + q * 8];
                rBv[i] = *(const uint4*)&g_Bx[(size_t)(n0 + row) * KTOT + (c + 1) * BK + q * 8];
            }
        }

        #pragma unroll
        for (int kk = 0; kk < 4; kk++) {
            uint32_t a[4][4], b[2][4];
            #pragma unroll
            for (int mt = 0; mt < 4; mt++) {
                int row = rA + mt * 16;
                ldsm4(a[mt], sA32 + row * 128 + ((kk * 32 + hbA) ^ ((row << 4) & 0x70)));
            }
            #pragma unroll
            for (int h = 0; h < 2; h++) {
                int row = rB + h * 16;
                ldsm4(b[h], sB32 + row * 128 + ((kk * 32 + hbB) ^ ((row << 4) & 0x70)));
            }
            #pragma unroll
            for (int mt = 0; mt < 4; mt++)
                #pragma unroll
                for (int nt = 0; nt < 4; nt++)
                    mma16816(acc[mt][nt], a[mt], b[nt >> 1][(nt & 1) * 2], b[nt >> 1][(nt & 1) * 2 + 1]);
        }
        __syncthreads();
    }

    const int er = lane >> 2;
    const int ec = (lane & 3) * 2;
    #pragma unroll
    for (int mt = 0; mt < 4; mt++) {
        int m = m0 + warp_m * 64 + mt * 16 + er;
        #pragma unroll
        for (int nt = 0; nt < 4; nt++) {
            int n = n0 + warp_n * 32 + nt * 8 + ec;
            float2 bias = *(const float2*)&g_bp[n];
            float2 o0 = make_float2(acc[mt][nt][0] + bias.x, acc[mt][nt][1] + bias.y);
            float2 o1 = make_float2(acc[mt][nt][2] + bias.x, acc[mt][nt][3] + bias.y);
            *(float2*)&g_xp[(size_t)m * NC + n]       = o0;
            *(float2*)&g_xp[(size_t)(m + 8) * NC + n] = o1;
        }
    }
}

// ============================ recurrent kernel: 2-group interleaved clusters ============================
// 8 clusters of 8 CTAs. Cluster owns 8 batches: group A = first 4, group B = last 4.
// Per step t: slot A (wait exch t-1, dot, sync, combine+bcast+arrive) then slot B.
// While A's exchange is in flight, all warps compute B's dot -> exchange latency hidden.
// Protocol per group = R10's proven mbarrier scheme: exchange e uses mbarG[e&1], parity (e>>1)&1.
__global__ void __cluster_dims__(CLUSTER, 1, 1) __launch_bounds__(RTHR, 1)
recur_kernel(float* __restrict__ out)
{
    extern __shared__ float sm[];
    // layout: hbufA[2][1024] | hbufB[2][1024] | pbufA[8][4][128] | pbufB[8][4][128] | mbars
    float* hbA = sm;
    float* hbB = sm + 2048;
    float* pbA = sm + 4096;
    float* pbB = sm + 8192;
    unsigned long long* mb = (unsigned long long*)(sm + 12288);  // [g2][buf2]

    const int tid  = threadIdx.x;
    const int part = blockIdx.x & (CLUSTER - 1);
    const int grp  = blockIdx.x >> 3;     // 0..7
    const int kc   = tid >> 7;            // 0..7
    const int c    = tid & 127;           // 0..127

    const uint32_t mb32  = smem_u32(mb);
    const uint32_t hbA32 = smem_u32(hbA);
    const uint32_t hbB32 = smem_u32(hbB);

    float w[32];
    {
        const float* src = &g_Whp[(size_t)((part * 8 + kc) * 32) * 128 + c];
        #pragma unroll
        for (int i = 0; i < 32; i++) w[i] = src[(size_t)i * 128];
    }

    for (int i = tid; i < 4096; i += RTHR) sm[i] = 0.0f;   // zero both h buffers
    if (tid == 0) {
        #pragma unroll
        for (int q = 0; q < 4; q++)
            asm volatile("mbarrier.init.shared.b64 [%0], %1;"
                         :: "r"(mb32 + q * 8), "r"(8u) : "memory");
    }
    __syncthreads();
    asm volatile("barrier.cluster.arrive.aligned;" ::: "memory");
    asm volatile("barrier.cluster.wait.aligned;" ::: "memory");

    // combine identity (threads 0..127): warp = cb (batch), lane = cu (unit)
    const int cb = tid >> 5;
    const int cu = tid & 31;
    const int j  = part * 32 + cu;
    const int bgA = grp * 8 + cb;        // group A global batch
    const int bgB = grp * 8 + 4 + cb;    // group B global batch
    float csA = 0.0f, csB = 0.0f;

    const size_t HT_OFF = (size_t)TSTEPS * BATCH * DHID;

    for (int t = 0; t < TSTEPS; t++) {
        const int p = t & 1;

        // ======================= slot A =======================
        if (t > 0)   // wait exchange t-1 of group A
            MBAR_WAIT_CL(mb32 + (uint32_t)(((t - 1) & 1) * 8), (uint32_t)(((t - 1) >> 1) & 1));

        float4 xpA;
        if (tid < 128)
            xpA = *(const float4*)&g_xp[((size_t)t * BATCH + bgA) * NC + part * 128 + cu * 4];

        {   // stage 1 A
            unsigned long long acc01 = 0ull, acc23 = 0ull;
            const float* hrow = hbA + p * 1024 + kc * 128;
            #pragma unroll
            for (int i = 0; i < 32; i++) {
                ulonglong2 hh = *(const ulonglong2*)&hrow[i * 4];
                unsigned long long ww;
                asm("mov.b64 %0, {%1, %1};" : "=l"(ww) : "f"(w[i]));
                asm("fma.rn.f32x2 %0, %1, %2, %0;" : "+l"(acc01) : "l"(ww), "l"(hh.x));
                asm("fma.rn.f32x2 %0, %1, %2, %0;" : "+l"(acc23) : "l"(ww), "l"(hh.y));
            }
            float a0, a1, a2, a3;
            asm("mov.b64 {%0, %1}, %2;" : "=f"(a0), "=f"(a1) : "l"(acc01));
            asm("mov.b64 {%0, %1}, %2;" : "=f"(a2), "=f"(a3) : "l"(acc23));
            pbA[kc * 512 + 0 * 128 + c] = a0;
            pbA[kc * 512 + 1 * 128 + c] = a1;
            pbA[kc * 512 + 2 * 128 + c] = a2;
            pbA[kc * 512 + 3 * 128 + c] = a3;
        }
        __syncthreads();

        if (tid < 128) {   // stage 2 A (warps 4..31 flow on to slot B's stage 1)
            float4 s = make_float4(0.f, 0.f, 0.f, 0.f);
            #pragma unroll
            for (int q = 0; q < 8; q++) {
                float4 p4 = *(const float4*)&pbA[q * 512 + cb * 128 + cu * 4];
                s.x += p4.x; s.y += p4.y; s.z += p4.z; s.w += p4.w;
            }
            float fv = 1.0f / (1.0f + __expf(-(s.x + xpA.x)));
            float iv = 1.0f / (1.0f + __expf(-(s.y + xpA.y)));
            float ov = 1.0f / (1.0f + __expf(-(s.w + xpA.w)));
            float gt, ht;
            asm("tanh.approx.f32 %0, %1;" : "=f"(gt) : "f"(s.z + xpA.z));
            csA = fv * csA + iv * gt;
            asm("tanh.approx.f32 %0, %1;" : "=f"(ht) : "f"(csA));
            float h = ov * ht;

            out[(size_t)t * (BATCH * DHID) + (size_t)bgA * DHID + j] = h;
            if (t == TSTEPS - 1) {
                out[HT_OFF + (size_t)bgA * DHID + j] = h;
                out[HT_OFF + (size_t)BATCH * DHID + (size_t)bgA * DHID + j] = csA;
            }

            unsigned dst = hbA32 + (unsigned)(((1 - p) * 1024 + j * 4 + cb) * 4);
            #pragma unroll
            for (int r = 0; r < CLUSTER; r++) {
                unsigned rem;
                asm("mapa.shared::cluster.u32 %0, %1, %2;" : "=r"(rem) : "r"(dst), "r"(r));
                asm volatile("st.shared::cluster.f32 [%0], %1;" :: "r"(rem), "f"(h) : "memory");
            }
            __syncwarp();
            if (cu < 2) {   // arrive exchange t of group A at peer cb*2+cu
                unsigned peer = (unsigned)(cb * 2 + cu);
                asm volatile("fence.acq_rel.cluster;" ::: "memory");
                asm volatile("{ .reg .b32 r; mapa.shared::cluster.u32 r, %0, %1;\n\t"
                             "mbarrier.arrive.shared::cluster.b64 _, [r]; }"
                             :: "r"(mb32 + (unsigned)(p * 8)), "r"(peer) : "memory");
            }
        }

        // ======================= slot B =======================
        if (t > 0)   // wait exchange t-1 of group B
            MBAR_WAIT_CL(mb32 + 16u + (uint32_t)(((t - 1) & 1) * 8), (uint32_t)(((t - 1) >> 1) & 1));

        float4 xpB;
        if (tid < 128)
            xpB = *(const float4*)&g_xp[((size_t)t * BATCH + bgB) * NC + part * 128 + cu * 4];

        {   // stage 1 B
            unsigned long long acc01 = 0ull, acc23 = 0ull;
            const float* hrow = hbB + p * 1024 + kc * 128;
            #pragma unroll
            for (int i = 0; i < 32; i++) {
                ulonglong2 hh = *(const ulonglong2*)&hrow[i * 4];
                unsigned long long ww;
                asm("mov.b64 %0, {%1, %1};" : "=l"(ww) : "f"(w[i]));
                asm("fma.rn.f32x2 %0, %1, %2, %0;" : "+l"(acc01) : "l"(ww), "l"(hh.x));
                asm("fma.rn.f32x2 %0, %1, %2, %0;" : "+l"(acc23) : "l"(ww), "l"(hh.y));
            }
            float a0, a1, a2, a3;
            asm("mov.b64 {%0, %1}, %2;" : "=f"(a0), "=f"(a1) : "l"(acc01));
            asm("mov.b64 {%0, %1}, %2;" : "=f"(a2), "=f"(a3) : "l"(acc23));
            pbB[kc * 512 + 0 * 128 + c] = a0;
            pbB[kc * 512 + 1 * 128 + c] = a1;
            pbB[kc * 512 + 2 * 128 + c] = a2;
            pbB[kc * 512 + 3 * 128 + c] = a3;
        }
        __syncthreads();

        if (tid < 128) {   // stage 2 B (warps 4..31 flow on to next step's slot A)
            float4 s = make_float4(0.f, 0.f, 0.f, 0.f);
            #pragma unroll
            for (int q = 0; q < 8; q++) {
                float4 p4 = *(const float4*)&pbB[q * 512 + cb * 128 + cu * 4];
                s.x += p4.x; s.y += p4.y; s.z += p4.z; s.w += p4.w;
            }
            float fv = 1.0f / (1.0f + __expf(-(s.x + xpB.x)));
            float iv = 1.0f / (1.0f + __expf(-(s.y + xpB.y)));
            float ov = 1.0f / (1.0f + __expf(-(s.w + xpB.w)));
            float gt, ht;
            asm("tanh.approx.f32 %0, %1;" : "=f"(gt) : "f"(s.z + xpB.z));
            csB = fv * csB + iv * gt;
            asm("tanh.approx.f32 %0, %1;" : "=f"(ht) : "f"(csB));
            float h = ov * ht;

            out[(size_t)t * (BATCH * DHID) + (size_t)bgB * DHID + j] = h;
            if (t == TSTEPS - 1) {
                out[HT_OFF + (size_t)bgB * DHID + j] = h;
                out[HT_OFF + (size_t)BATCH * DHID + (size_t)bgB * DHID + j] = csB;
            }

            unsigned dst = hbB32 + (unsigned)(((1 - p) * 1024 + j * 4 + cb) * 4);
            #pragma unroll
            for (int r = 0; r < CLUSTER; r++) {
                unsigned rem;
                asm("mapa.shared::cluster.u32 %0, %1, %2;" : "=r"(rem) : "r"(dst), "r"(r));
                asm volatile("st.shared::cluster.f32 [%0], %1;" :: "r"(rem), "f"(h) : "memory");
            }
            __syncwarp();
            if (cu < 2) {   // arrive exchange t of group B at peer cb*2+cu
                unsigned peer = (unsigned)(cb * 2 + cu);
                asm volatile("fence.acq_rel.cluster;" ::: "memory");
                asm volatile("{ .reg .b32 r; mapa.shared::cluster.u32 r, %0, %1;\n\t"
                             "mbarrier.arrive.shared::cluster.b64 _, [r]; }"
                             :: "r"(mb32 + 16u + (unsigned)(p * 8)), "r"(peer) : "memory");
            }
        }
    }

    // exit barrier: no CTA leaves while peers' remote ops could still target its smem
    asm volatile("barrier.cluster.arrive.aligned;" ::: "memory");
    asm volatile("barrier.cluster.wait.aligned;" ::: "memory");
}

// ============================ launch ============================
#define RSMEM (12288 * 4 + 64)

extern "C" void kernel_launch(void* const* d_in, const int* in_sizes, int n_in,
                              void* d_out, int out_size)
{
    const float* X  = (const float*)d_in[0];
    const float* Wf = (const float*)d_in[1];
    const float* bf = (const float*)d_in[2];
    const float* Wi = (const float*)d_in[3];
    const float* bi = (const float*)d_in[4];
    const float* Wg = (const float*)d_in[5];
    const float* bg = (const float*)d_in[6];
    const float* Wo = (const float*)d_in[7];
    const float* bo = (const float*)d_in[8];
    float* out = (float*)d_out;

    cudaFuncSetAttribute(recur_kernel, cudaFuncAttributeMaxDynamicSharedMemorySize, RSMEM);

    packB_kernel<<<(DIN * NC + 255) / 256, 256>>>(Wf, bf, Wi, bi, Wg, bg, Wo, bo);
    packA_kernel<<<(M_TOTAL * (DIN / 4) + 255) / 256, 256>>>(X);

    dim3 ggrid(NC / 128, M_TOTAL / 128);
    xproj_mma<<<ggrid, XT>>>();

    recur_kernel<<<NCTA, RTHR, RSMEM>>>(out);
}

// round 14
// speedup vs baseline: 1.9274x; 1.1298x over previous
#include <cuda_runtime.h>
#include <cuda_bf16.h>
#include <cstddef>
#include <cstdint>

#define TSTEPS 1024
#define BATCH  64
#define DIN    256
#define DHID   256
#define NC     1024
#define M_TOTAL (TSTEPS * BATCH)
#define KTOT   768            // split-bf16 virtual K: [Xhi|Xhi|Xlo] x [Whi;Wlo;Whi]

#define CLUSTER 8
#define NCTA    64            // 8 clusters x 8 CTAs; each cluster owns 8 batches (2 groups of 4)
#define RTHR    1024          // 32 warps: kc(8) x c(128)
#define XBYTES  4096u         // tx bytes per exchange per CTA: 8 CTAs x 128 floats

// packed column: pc = part*128 + u*4 + gate, j = part*32 + u, gate in {f,i,g,o}

__device__ float         g_xp[(size_t)M_TOTAL * NC];     // x-proj + bias [m][pc]
__device__ __nv_bfloat16 g_Ax[(size_t)M_TOTAL * KTOT];   // split-bf16 A' [m][k']
__device__ __nv_bfloat16 g_Bx[(size_t)NC * KTOT];        // split-bf16 B' [pc][k']
__device__ float         g_Whp[DHID * NC];               // fp32 Wh [part][kc8][i32][c128]
__device__ float         g_bp[NC];

// ============================ helpers ============================
__device__ __forceinline__ uint32_t smem_u32(const void* p) {
    uint32_t a;
    asm("{ .reg .u64 t; cvta.to.shared.u64 t, %1; cvt.u32.u64 %0, t; }" : "=r"(a) : "l"(p));
    return a;
}
#define SW128(off) ((off) ^ (((off) >> 3) & 0x70))

__device__ __forceinline__ void ldsm4(uint32_t* r, uint32_t addr) {
    asm volatile("ldmatrix.sync.aligned.m8n8.x4.shared.b16 {%0,%1,%2,%3}, [%4];"
                 : "=r"(r[0]), "=r"(r[1]), "=r"(r[2]), "=r"(r[3]) : "r"(addr));
}
__device__ __forceinline__ void mma16816(float* c, const uint32_t* a, uint32_t b0, uint32_t b1) {
    asm volatile("mma.sync.aligned.m16n8k16.row.col.f32.bf16.bf16.f32 "
                 "{%0,%1,%2,%3}, {%4,%5,%6,%7}, {%8,%9}, {%0,%1,%2,%3};"
                 : "+f"(c[0]), "+f"(c[1]), "+f"(c[2]), "+f"(c[3])
                 : "r"(a[0]), "r"(a[1]), "r"(a[2]), "r"(a[3]), "r"(b0), "r"(b1));
}

// local mbarrier wait (tx-completion pattern; acquire.cta suffices like TMA consumers)
#define MBAR_WAIT(a, ph) do {                                                     \
    uint32_t _m = (a), _p = (ph), _d;                                             \
    asm volatile("{\n\t.reg .pred p;\n\t"                                         \
        "mbarrier.try_wait.parity.acquire.cta.shared::cta.b64 p, [%1], %2;\n\t"   \
        "selp.b32 %0, 1, 0, p;\n\t}" : "=r"(_d) : "r"(_m), "r"(_p) : "memory");   \
    if (!_d) {                                                                    \
        asm volatile("{\n\t.reg .pred P1;\n\tWL_%=:\n\t"                          \
            "mbarrier.try_wait.parity.acquire.cta.shared::cta.b64 P1, [%0], %1, 0x989680;\n\t" \
            "@P1 bra.uni WD_%=;\n\tbra.uni WL_%=;\n\tWD_%=:\n\t}"                 \
            :: "r"(_m), "r"(_p) : "memory");                                      \
    }                                                                             \
} while (0)

#define MBAR_EXPECT(a, n) \
    asm volatile("mbarrier.arrive.expect_tx.shared.b64 _, [%0], %1;" \
                 :: "r"(a), "r"((uint32_t)(n)) : "memory")

// async store with tx completion at the peer's mbarrier (no fence, no remote arrive)
__device__ __forceinline__ void st_async_f32(uint32_t dst_local, uint32_t mbar_local,
                                             unsigned peer, float v) {
    asm volatile("{ .reg .b32 rd, rm;\n\t"
                 "mapa.shared::cluster.u32 rd, %0, %2;\n\t"
                 "mapa.shared::cluster.u32 rm, %1, %2;\n\t"
                 "st.async.shared::cluster.mbarrier::complete_tx::bytes.f32 [rd], %3, [rm]; }"
                 :: "r"(dst_local), "r"(mbar_local), "r"(peer), "f"(v) : "memory");
}

// ============================ pack kernels ============================
__global__ void packB_kernel(const float* __restrict__ Wf, const float* __restrict__ bf,
                             const float* __restrict__ Wi, const float* __restrict__ bi,
                             const float* __restrict__ Wg, const float* __restrict__ bg,
                             const float* __restrict__ Wo, const float* __restrict__ bo)
{
    int idx = blockIdx.x * blockDim.x + threadIdx.x;
    if (idx >= DIN * NC) return;
    int k    = idx >> 10;
    int pc   = idx & (NC - 1);
    int part = pc >> 7;
    int c    = pc & 127;
    int u    = c >> 2;
    int gate = c & 3;
    int j    = part * 32 + u;
    const float* W = (gate == 0) ? Wf : (gate == 1) ? Wi : (gate == 2) ? Wg : Wo;
    const float* b = (gate == 0) ? bf : (gate == 1) ? bi : (gate == 2) ? bg : bo;

    float wx = W[(size_t)k * DHID + j];
    __nv_bfloat16 hi = __float2bfloat16_rn(wx);
    float lo = wx - __bfloat162float(hi);
    g_Bx[(size_t)pc * KTOT + k]       = hi;                        // pairs with Xhi
    g_Bx[(size_t)pc * KTOT + 256 + k] = __float2bfloat16_rn(lo);   // pairs with Xhi
    g_Bx[(size_t)pc * KTOT + 512 + k] = hi;                        // pairs with Xlo

    float wh = W[(size_t)(DIN + k) * DHID + j];
    int kc = k >> 5, i = k & 31;   // 8 chunks of 32 k
    g_Whp[(size_t)(((part * 8 + kc) * 32) + i) * 128 + c] = wh;
    if (k == 0) g_bp[pc] = b[j];
}

__global__ void packA_kernel(const float* __restrict__ X)
{
    int idx = blockIdx.x * blockDim.x + threadIdx.x;
    if (idx >= M_TOTAL * (DIN / 4)) return;
    int m  = idx >> 6;
    int kq = idx & 63;
    float4 v = *(const float4*)&X[(size_t)m * DIN + kq * 4];
    __nv_bfloat162 h0 = __floats2bfloat162_rn(v.x, v.y);
    __nv_bfloat162 h1 = __floats2bfloat162_rn(v.z, v.w);
    float lx = v.x - __bfloat162float(h0.x);
    float ly = v.y - __bfloat162float(h0.y);
    float lz = v.z - __bfloat162float(h1.x);
    float lw = v.w - __bfloat162float(h1.y);
    __nv_bfloat162 l0 = __floats2bfloat162_rn(lx, ly);
    __nv_bfloat162 l1 = __floats2bfloat162_rn(lz, lw);
    size_t base = (size_t)m * KTOT + kq * 4;
    *(__nv_bfloat162*)&g_Ax[base]       = h0;
    *(__nv_bfloat162*)&g_Ax[base + 2]   = h1;
    *(__nv_bfloat162*)&g_Ax[base + 256] = h0;
    *(__nv_bfloat162*)&g_Ax[base + 258] = h1;
    *(__nv_bfloat162*)&g_Ax[base + 512] = l0;
    *(__nv_bfloat162*)&g_Ax[base + 514] = l1;
}

// ============================ xproj GEMM: mma.sync bf16 (proven) ============================
#define XT 256
#define BK 64
#define NCHUNK (KTOT / BK)

__global__ __launch_bounds__(XT) void xproj_mma()
{
    __shared__ __align__(128) __nv_bfloat16 sAbuf[128 * 64];
    __shared__ __align__(128) __nv_bfloat16 sBbuf[128 * 64];

    const int tid    = threadIdx.x;
    const int wid    = tid >> 5;
    const int lane   = tid & 31;
    const int warp_m = wid >> 2;
    const int warp_n = wid & 3;
    const int n0     = blockIdx.x * 128;
    const int m0     = blockIdx.y * 128;

    const uint32_t sA32 = smem_u32(sAbuf);
    const uint32_t sB32 = smem_u32(sBbuf);
    char* sAp = (char*)sAbuf;
    char* sBp = (char*)sBbuf;

    const int g  = lane >> 3;
    const int lr = lane & 7;
    const int rA   = warp_m * 64 + (g & 1) * 8 + lr;
    const int hbA  = (g >> 1) * 16;
    const int rB   = warp_n * 32 + (g >> 1) * 8 + lr;
    const int hbB  = (g & 1) * 16;

    float acc[4][4][4];
    #pragma unroll
    for (int i = 0; i < 4; i++)
        #pragma unroll
        for (int jj = 0; jj < 4; jj++)
            #pragma unroll
            for (int q = 0; q < 4; q++) acc[i][jj][q] = 0.0f;

    uint4 rAv[4], rBv[4];
    #pragma unroll
    for (int i = 0; i < 4; i++) {
        int idx = tid + i * 256, row = idx >> 3, q = idx & 7;
        rAv[i] = *(const uint4*)&g_Ax[(size_t)(m0 + row) * KTOT + q * 8];
        rBv[i] = *(const uint4*)&g_Bx[(size_t)(n0 + row) * KTOT + q * 8];
    }

    for (int c = 0; c < NCHUNK; c++) {
        #pragma unroll
        for (int i = 0; i < 4; i++) {
            int idx = tid + i * 256, row = idx >> 3, q = idx & 7;
            *(uint4*)(sAp + SW128(row * 128 + q * 16)) = rAv[i];
            *(uint4*)(sBp + SW128(row * 128 + q * 16)) = rBv[i];
        }
        __syncthreads();

        if (c + 1 < NCHUNK) {
            #pragma unroll
            for (int i = 0; i < 4; i++) {
                int idx = tid + i * 256, row = idx >> 3, q = idx & 7;
                rAv[i] = *(const uint4*)&g_Ax[(size_t)(m0 + row) * KTOT + (c + 1) * BK + q * 8];
                rBv[i] = *(const uint4*)&g_Bx[(size_t)(n0 + row) * KTOT + (c + 1) * BK + q * 8];
            }
        }

        #pragma unroll
        for (int kk = 0; kk < 4; kk++) {
            uint32_t a[4][4], b[2][4];
            #pragma unroll
            for (int mt = 0; mt < 4; mt++) {
                int row = rA + mt * 16;
                ldsm4(a[mt], sA32 + row * 128 + ((kk * 32 + hbA) ^ ((row << 4) & 0x70)));
            }
            #pragma unroll
            for (int h = 0; h < 2; h++) {
                int row = rB + h * 16;
                ldsm4(b[h], sB32 + row * 128 + ((kk * 32 + hbB) ^ ((row << 4) & 0x70)));
            }
            #pragma unroll
            for (int mt = 0; mt < 4; mt++)
                #pragma unroll
                for (int nt = 0; nt < 4; nt++)
                    mma16816(acc[mt][nt], a[mt], b[nt >> 1][(nt & 1) * 2], b[nt >> 1][(nt & 1) * 2 + 1]);
        }
        __syncthreads();
    }

    const int er = lane >> 2;
    const int ec = (lane & 3) * 2;
    #pragma unroll
    for (int mt = 0; mt < 4; mt++) {
        int m = m0 + warp_m * 64 + mt * 16 + er;
        #pragma unroll
        for (int nt = 0; nt < 4; nt++) {
            int n = n0 + warp_n * 32 + nt * 8 + ec;
            float2 bias = *(const float2*)&g_bp[n];
            float2 o0 = make_float2(acc[mt][nt][0] + bias.x, acc[mt][nt][1] + bias.y);
            float2 o1 = make_float2(acc[mt][nt][2] + bias.x, acc[mt][nt][3] + bias.y);
            *(float2*)&g_xp[(size_t)m * NC + n]       = o0;
            *(float2*)&g_xp[(size_t)(m + 8) * NC + n] = o1;
        }
    }
}

// ============================ recurrent kernel: st.async tx-tracked exchange ============================
// 8 clusters of 8 CTAs, 2 interleaved groups per cluster (R13 structure). Exchange e of a
// group uses mbar slot e&1, phase e>>1, parity (e>>1)&1, tx = 4096 bytes; data delivered by
// st.async (async proxy) -> NO cluster-scope fence (no CCTL.IVALL), NO remote arrives.
// Re-arm: post-wait(ex e) thread 0 expect_tx on that slot for exchange e+2 (program-order safe).
__global__ void __cluster_dims__(CLUSTER, 1, 1) __launch_bounds__(RTHR, 1)
recur_kernel(float* __restrict__ out)
{
    extern __shared__ float sm[];
    float* hbA = sm;            // [2][1024]
    float* hbB = sm + 2048;     // [2][1024]
    float* pbA = sm + 4096;     // [8][4][128]
    float* pbB = sm + 8192;     // [8][4][128]
    unsigned long long* mb = (unsigned long long*)(sm + 12288);  // [g2][slot2]

    const int tid  = threadIdx.x;
    const int part = blockIdx.x & (CLUSTER - 1);
    const int grp  = blockIdx.x >> 3;
    const int kc   = tid >> 7;
    const int c    = tid & 127;

    const uint32_t mb32  = smem_u32(mb);
    const uint32_t hbA32 = smem_u32(hbA);
    const uint32_t hbB32 = smem_u32(hbB);

    float w[32];
    {
        const float* src = &g_Whp[(size_t)((part * 8 + kc) * 32) * 128 + c];
        #pragma unroll
        for (int i = 0; i < 32; i++) w[i] = src[(size_t)i * 128];
    }

    for (int i = tid; i < 4096; i += RTHR) sm[i] = 0.0f;
    if (tid == 0) {
        #pragma unroll
        for (int q = 0; q < 4; q++)
            asm volatile("mbarrier.init.shared.b64 [%0], %1;"
                         :: "r"(mb32 + q * 8), "r"(1u) : "memory");
        // arm exchanges 0 and 1 for both groups
        MBAR_EXPECT(mb32 + 0,  XBYTES);   // A slot 0 (ex 0)
        MBAR_EXPECT(mb32 + 8,  XBYTES);   // A slot 1 (ex 1)
        MBAR_EXPECT(mb32 + 16, XBYTES);   // B slot 0 (ex 0)
        MBAR_EXPECT(mb32 + 24, XBYTES);   // B slot 1 (ex 1)
    }
    __syncthreads();
    asm volatile("barrier.cluster.arrive.aligned;" ::: "memory");
    asm volatile("barrier.cluster.wait.aligned;" ::: "memory");

    const int cb = tid >> 5;
    const int cu = tid & 31;
    const int j  = part * 32 + cu;
    const int bgA = grp * 8 + cb;
    const int bgB = grp * 8 + 4 + cb;
    float csA = 0.0f, csB = 0.0f;

    const size_t HT_OFF = (size_t)TSTEPS * BATCH * DHID;

    for (int t = 0; t < TSTEPS; t++) {
        const int p = t & 1;

        // ======================= slot A =======================
        if (t > 0) {
            MBAR_WAIT(mb32 + (uint32_t)(((t - 1) & 1) * 8), (uint32_t)(((t - 1) >> 1) & 1));
            if (tid == 0) MBAR_EXPECT(mb32 + (uint32_t)(((t - 1) & 1) * 8), XBYTES);  // arm ex t+1
        }

        float4 xpA;
        if (tid < 128)
            xpA = *(const float4*)&g_xp[((size_t)t * BATCH + bgA) * NC + part * 128 + cu * 4];

        {   // stage 1 A
            unsigned long long acc01 = 0ull, acc23 = 0ull;
            const float* hrow = hbA + p * 1024 + kc * 128;
            #pragma unroll
            for (int i = 0; i < 32; i++) {
                ulonglong2 hh = *(const ulonglong2*)&hrow[i * 4];
                unsigned long long ww;
                asm("mov.b64 %0, {%1, %1};" : "=l"(ww) : "f"(w[i]));
                asm("fma.rn.f32x2 %0, %1, %2, %0;" : "+l"(acc01) : "l"(ww), "l"(hh.x));
                asm("fma.rn.f32x2 %0, %1, %2, %0;" : "+l"(acc23) : "l"(ww), "l"(hh.y));
            }
            float a0, a1, a2, a3;
            asm("mov.b64 {%0, %1}, %2;" : "=f"(a0), "=f"(a1) : "l"(acc01));
            asm("mov.b64 {%0, %1}, %2;" : "=f"(a2), "=f"(a3) : "l"(acc23));
            pbA[kc * 512 + 0 * 128 + c] = a0;
            pbA[kc * 512 + 1 * 128 + c] = a1;
            pbA[kc * 512 + 2 * 128 + c] = a2;
            pbA[kc * 512 + 3 * 128 + c] = a3;
        }
        __syncthreads();

        if (tid < 128) {   // stage 2 A
            float4 s = make_float4(0.f, 0.f, 0.f, 0.f);
            #pragma unroll
            for (int q = 0; q < 8; q++) {
                float4 p4 = *(const float4*)&pbA[q * 512 + cb * 128 + cu * 4];
                s.x += p4.x; s.y += p4.y; s.z += p4.z; s.w += p4.w;
            }
            float fv = 1.0f / (1.0f + __expf(-(s.x + xpA.x)));
            float iv = 1.0f / (1.0f + __expf(-(s.y + xpA.y)));
            float ov = 1.0f / (1.0f + __expf(-(s.w + xpA.w)));
            float gt, ht;
            asm("tanh.approx.f32 %0, %1;" : "=f"(gt) : "f"(s.z + xpA.z));
            csA = fv * csA + iv * gt;
            asm("tanh.approx.f32 %0, %1;" : "=f"(ht) : "f"(csA));
            float h = ov * ht;

            if (t < TSTEPS - 1) {   // broadcast h via st.async (data + tx to peer mbar)
                unsigned dst = hbA32 + (unsigned)(((1 - p) * 1024 + j * 4 + cb) * 4);
                unsigned mba = mb32 + (unsigned)(p * 8);
                #pragma unroll
                for (int r = 0; r < CLUSTER; r++)
                    st_async_f32(dst, mba, (unsigned)r, h);
            }

            out[(size_t)t * (BATCH * DHID) + (size_t)bgA * DHID + j] = h;
            if (t == TSTEPS - 1) {
                out[HT_OFF + (size_t)bgA * DHID + j] = h;
                out[HT_OFF + (size_t)BATCH * DHID + (size_t)bgA * DHID + j] = csA;
            }
        }

        // ======================= slot B =======================
        if (t > 0) {
            MBAR_WAIT(mb32 + 16u + (uint32_t)(((t - 1) & 1) * 8), (uint32_t)(((t - 1) >> 1) & 1));
            if (tid == 0) MBAR_EXPECT(mb32 + 16u + (uint32_t)(((t - 1) & 1) * 8), XBYTES);
        }

        float4 xpB;
        if (tid < 128)
            xpB = *(const float4*)&g_xp[((size_t)t * BATCH + bgB) * NC + part * 128 + cu * 4];

        {   // stage 1 B
            unsigned long long acc01 = 0ull, acc23 = 0ull;
            const float* hrow = hbB + p * 1024 + kc * 128;
            #pragma unroll
            for (int i = 0; i < 32; i++) {
                ulonglong2 hh = *(const ulonglong2*)&hrow[i * 4];
                unsigned long long ww;
                asm("mov.b64 %0, {%1, %1};" : "=l"(ww) : "f"(w[i]));
                asm("fma.rn.f32x2 %0, %1, %2, %0;" : "+l"(acc01) : "l"(ww), "l"(hh.x));
                asm("fma.rn.f32x2 %0, %1, %2, %0;" : "+l"(acc23) : "l"(ww), "l"(hh.y));
            }
            float a0, a1, a2, a3;
            asm("mov.b64 {%0, %1}, %2;" : "=f"(a0), "=f"(a1) : "l"(acc01));
            asm("mov.b64 {%0, %1}, %2;" : "=f"(a2), "=f"(a3) : "l"(acc23));
            pbB[kc * 512 + 0 * 128 + c] = a0;
            pbB[kc * 512 + 1 * 128 + c] = a1;
            pbB[kc * 512 + 2 * 128 + c] = a2;
            pbB[kc * 512 + 3 * 128 + c] = a3;
        }
        __syncthreads();

        if (tid < 128) {   // stage 2 B
            float4 s = make_float4(0.f, 0.f, 0.f, 0.f);
            #pragma unroll
            for (int q = 0; q < 8; q++) {
                float4 p4 = *(const float4*)&pbB[q * 512 + cb * 128 + cu * 4];
                s.x += p4.x; s.y += p4.y; s.z += p4.z; s.w += p4.w;
            }
            float fv = 1.0f / (1.0f + __expf(-(s.x + xpB.x)));
            float iv = 1.0f / (1.0f + __expf(-(s.y + xpB.y)));
            float ov = 1.0f / (1.0f + __expf(-(s.w + xpB.w)));
            float gt, ht;
            asm("tanh.approx.f32 %0, %1;" : "=f"(gt) : "f"(s.z + xpB.z));
            csB = fv * csB + iv * gt;
            asm("tanh.approx.f32 %0, %1;" : "=f"(ht) : "f"(csB));
            float h = ov * ht;

            if (t < TSTEPS - 1) {
                unsigned dst = hbB32 + (unsigned)(((1 - p) * 1024 + j * 4 + cb) * 4);
                unsigned mba = mb32 + 16u + (unsigned)(p * 8);
                #pragma unroll
                for (int r = 0; r < CLUSTER; r++)
                    st_async_f32(dst, mba, (unsigned)r, h);
            }

            out[(size_t)t * (BATCH * DHID) + (size_t)bgB * DHID + j] = h;
            if (t == TSTEPS - 1) {
                out[HT_OFF + (size_t)bgB * DHID + j] = h;
                out[HT_OFF + (size_t)BATCH * DHID + (size_t)bgB * DHID + j] = csB;
            }
        }
    }

    // exit barrier: all CTAs alive until every peer is past its last wait
    asm volatile("barrier.cluster.arrive.aligned;" ::: "memory");
    asm volatile("barrier.cluster.wait.aligned;" ::: "memory");
}

// ============================ launch ============================
#define RSMEM (12288 * 4 + 64)

extern "C" void kernel_launch(void* const* d_in, const int* in_sizes, int n_in,
                              void* d_out, int out_size)
{
    const float* X  = (const float*)d_in[0];
    const float* Wf = (const float*)d_in[1];
    const float* bf = (const float*)d_in[2];
    const float* Wi = (const float*)d_in[3];
    const float* bi = (const float*)d_in[4];
    const float* Wg = (const float*)d_in[5];
    const float* bg = (const float*)d_in[6];
    const float* Wo = (const float*)d_in[7];
    const float* bo = (const float*)d_in[8];
    float* out = (float*)d_out;

    cudaFuncSetAttribute(recur_kernel, cudaFuncAttributeMaxDynamicSharedMemorySize, RSMEM);

    packB_kernel<<<(DIN * NC + 255) / 256, 256>>>(Wf, bf, Wi, bi, Wg, bg, Wo, bo);
    packA_kernel<<<(M_TOTAL * (DIN / 4) + 255) / 256, 256>>>(X);

    dim3 ggrid(NC / 128, M_TOTAL / 128);
    xproj_mma<<<ggrid, XT>>>();

    recur_kernel<<<NCTA, RTHR, RSMEM>>>(out);
}

// round 16
// speedup vs baseline: 2.0246x; 1.0504x over previous
#include <cuda_runtime.h>
#include <cuda_bf16.h>
#include <cstddef>
#include <cstdint>

#define TSTEPS 1024
#define BATCH  64
#define DIN    256
#define DHID   256
#define NC     1024
#define M_TOTAL (TSTEPS * BATCH)
#define KTOT   768            // split-bf16 virtual K: [Xhi|Xhi|Xlo] x [Whi;Wlo;Whi]

#define CLUSTER 8
#define NCTA    64            // 8 clusters x 8 CTAs; each cluster owns 8 batches (2 groups of 4)
#define RTHR    1024          // 32 warps: kc(8) x c(128)
#define XBYTES  4096u         // tx bytes per exchange per CTA: 8 CTAs x 128 floats

// packed column: pc = part*128 + u*4 + gate, j = part*32 + u, gate in {f,i,g,o}
// R16 = resubmission of R15 (double container failure; code audit vs passing R14 found
// no new hazard — precedent R6->R7 identical resubmit passed).

__device__ float         g_xp[(size_t)M_TOTAL * NC];     // x-proj + bias [m][pc]
__device__ __nv_bfloat16 g_Ax[(size_t)M_TOTAL * KTOT];   // split-bf16 A' [m][k']
__device__ __nv_bfloat16 g_Bx[(size_t)NC * KTOT];        // split-bf16 B' [pc][k']
__device__ float         g_Whp[DHID * NC];               // fp32 Wh [part][kc8][i32][c128]
__device__ float         g_bp[NC];

// ============================ helpers ============================
__device__ __forceinline__ uint32_t smem_u32(const void* p) {
    uint32_t a;
    asm("{ .reg .u64 t; cvta.to.shared.u64 t, %1; cvt.u32.u64 %0, t; }" : "=r"(a) : "l"(p));
    return a;
}
#define SW128(off) ((off) ^ (((off) >> 3) & 0x70))

__device__ __forceinline__ void ldsm4(uint32_t* r, uint32_t addr) {
    asm volatile("ldmatrix.sync.aligned.m8n8.x4.shared.b16 {%0,%1,%2,%3}, [%4];"
                 : "=r"(r[0]), "=r"(r[1]), "=r"(r[2]), "=r"(r[3]) : "r"(addr));
}
__device__ __forceinline__ void mma16816(float* c, const uint32_t* a, uint32_t b0, uint32_t b1) {
    asm volatile("mma.sync.aligned.m16n8k16.row.col.f32.bf16.bf16.f32 "
                 "{%0,%1,%2,%3}, {%4,%5,%6,%7}, {%8,%9}, {%0,%1,%2,%3};"
                 : "+f"(c[0]), "+f"(c[1]), "+f"(c[2]), "+f"(c[3])
                 : "r"(a[0]), "r"(a[1]), "r"(a[2]), "r"(a[3]), "r"(b0), "r"(b1));
}

// local mbarrier wait (tx-completion pattern; acquire.cta suffices like TMA consumers)
#define MBAR_WAIT(a, ph) do {                                                     \
    uint32_t _m = (a), _p = (ph), _d;                                             \
    asm volatile("{\n\t.reg .pred p;\n\t"                                         \
        "mbarrier.try_wait.parity.acquire.cta.shared::cta.b64 p, [%1], %2;\n\t"   \
        "selp.b32 %0, 1, 0, p;\n\t}" : "=r"(_d) : "r"(_m), "r"(_p) : "memory");   \
    if (!_d) {                                                                    \
        asm volatile("{\n\t.reg .pred P1;\n\tWL_%=:\n\t"                          \
            "mbarrier.try_wait.parity.acquire.cta.shared::cta.b64 P1, [%0], %1, 0x989680;\n\t" \
            "@P1 bra.uni WD_%=;\n\tbra.uni WL_%=;\n\tWD_%=:\n\t}"                 \
            :: "r"(_m), "r"(_p) : "memory");                                      \
    }                                                                             \
} while (0)

#define MBAR_EXPECT(a, n) \
    asm volatile("mbarrier.arrive.expect_tx.shared.b64 _, [%0], %1;" \
                 :: "r"(a), "r"((uint32_t)(n)) : "memory")

// async store with tx completion at the peer's mbarrier (no fence, no remote arrive)
__device__ __forceinline__ void st_async_f32(uint32_t dst_local, uint32_t mbar_local,
                                             unsigned peer, float v) {
    asm volatile("{ .reg .b32 rd, rm;\n\t"
                 "mapa.shared::cluster.u32 rd, %0, %2;\n\t"
                 "mapa.shared::cluster.u32 rm, %1, %2;\n\t"
                 "st.async.shared::cluster.mbarrier::complete_tx::bytes.f32 [rd], %3, [rm]; }"
                 :: "r"(dst_local), "r"(mbar_local), "r"(peer), "f"(v) : "memory");
}

// ============================ pack kernels ============================
__global__ void packB_kernel(const float* __restrict__ Wf, const float* __restrict__ bf,
                             const float* __restrict__ Wi, const float* __restrict__ bi,
                             const float* __restrict__ Wg, const float* __restrict__ bg,
                             const float* __restrict__ Wo, const float* __restrict__ bo)
{
    int idx = blockIdx.x * blockDim.x + threadIdx.x;
    if (idx >= DIN * NC) return;
    int k    = idx >> 10;
    int pc   = idx & (NC - 1);
    int part = pc >> 7;
    int c    = pc & 127;
    int u    = c >> 2;
    int gate = c & 3;
    int j    = part * 32 + u;
    const float* W = (gate == 0) ? Wf : (gate == 1) ? Wi : (gate == 2) ? Wg : Wo;
    const float* b = (gate == 0) ? bf : (gate == 1) ? bi : (gate == 2) ? bg : bo;

    float wx = W[(size_t)k * DHID + j];
    __nv_bfloat16 hi = __float2bfloat16_rn(wx);
    float lo = wx - __bfloat162float(hi);
    g_Bx[(size_t)pc * KTOT + k]       = hi;                        // pairs with Xhi
    g_Bx[(size_t)pc * KTOT + 256 + k] = __float2bfloat16_rn(lo);   // pairs with Xhi
    g_Bx[(size_t)pc * KTOT + 512 + k] = hi;                        // pairs with Xlo

    float wh = W[(size_t)(DIN + k) * DHID + j];
    int kc = k >> 5, i = k & 31;   // 8 chunks of 32 k
    g_Whp[(size_t)(((part * 8 + kc) * 32) + i) * 128 + c] = wh;
    if (k == 0) g_bp[pc] = b[j];
}

__global__ void packA_kernel(const float* __restrict__ X)
{
    int idx = blockIdx.x * blockDim.x + threadIdx.x;
    if (idx >= M_TOTAL * (DIN / 4)) return;
    int m  = idx >> 6;
    int kq = idx & 63;
    float4 v = *(const float4*)&X[(size_t)m * DIN + kq * 4];
    __nv_bfloat162 h0 = __floats2bfloat162_rn(v.x, v.y);
    __nv_bfloat162 h1 = __floats2bfloat162_rn(v.z, v.w);
    float lx = v.x - __bfloat162float(h0.x);
    float ly = v.y - __bfloat162float(h0.y);
    float lz = v.z - __bfloat162float(h1.x);
    float lw = v.w - __bfloat162float(h1.y);
    __nv_bfloat162 l0 = __floats2bfloat162_rn(lx, ly);
    __nv_bfloat162 l1 = __floats2bfloat162_rn(lz, lw);
    size_t base = (size_t)m * KTOT + kq * 4;
    *(__nv_bfloat162*)&g_Ax[base]       = h0;
    *(__nv_bfloat162*)&g_Ax[base + 2]   = h1;
    *(__nv_bfloat162*)&g_Ax[base + 256] = h0;
    *(__nv_bfloat162*)&g_Ax[base + 258] = h1;
    *(__nv_bfloat162*)&g_Ax[base + 512] = l0;
    *(__nv_bfloat162*)&g_Ax[base + 514] = l1;
}

// ============================ xproj GEMM: mma.sync bf16 (proven) ============================
#define XT 256
#define BK 64
#define NCHUNK (KTOT / BK)

__global__ __launch_bounds__(XT) void xproj_mma()
{
    __shared__ __align__(128) __nv_bfloat16 sAbuf[128 * 64];
    __shared__ __align__(128) __nv_bfloat16 sBbuf[128 * 64];

    const int tid    = threadIdx.x;
    const int wid    = tid >> 5;
    const int lane   = tid & 31;
    const int warp_m = wid >> 2;
    const int warp_n = wid & 3;
    const int n0     = blockIdx.x * 128;
    const int m0     = blockIdx.y * 128;

    const uint32_t sA32 = smem_u32(sAbuf);
    const uint32_t sB32 = smem_u32(sBbuf);
    char* sAp = (char*)sAbuf;
    char* sBp = (char*)sBbuf;

    const int g  = lane >> 3;
    const int lr = lane & 7;
    const int rA   = warp_m * 64 + (g & 1) * 8 + lr;
    const int hbA  = (g >> 1) * 16;
    const int rB   = warp_n * 32 + (g >> 1) * 8 + lr;
    const int hbB  = (g & 1) * 16;

    float acc[4][4][4];
    #pragma unroll
    for (int i = 0; i < 4; i++)
        #pragma unroll
        for (int jj = 0; jj < 4; jj++)
            #pragma unroll
            for (int q = 0; q < 4; q++) acc[i][jj][q] = 0.0f;

    uint4 rAv[4], rBv[4];
    #pragma unroll
    for (int i = 0; i < 4; i++) {
        int idx = tid + i * 256, row = idx >> 3, q = idx & 7;
        rAv[i] = *(const uint4*)&g_Ax[(size_t)(m0 + row) * KTOT + q * 8];
        rBv[i] = *(const uint4*)&g_Bx[(size_t)(n0 + row) * KTOT + q * 8];
    }

    for (int c = 0; c < NCHUNK; c++) {
        #pragma unroll
        for (int i = 0; i < 4; i++) {
            int idx = tid + i * 256, row = idx >> 3, q = idx & 7;
            *(uint4*)(sAp + SW128(row * 128 + q * 16)) = rAv[i];
            *(uint4*)(sBp + SW128(row * 128 + q * 16)) = rBv[i];
        }
        __syncthreads();

        if (c + 1 < NCHUNK) {
            #pragma unroll
            for (int i = 0; i < 4; i++) {
                int idx = tid + i * 256, row = idx >> 3, q = idx & 7;
                rAv[i] = *(const uint4*)&g_Ax[(size_t)(m0 + row) * KTOT + (c + 1) * BK + q * 8];
                rBv[i] = *(const uint4*)&g_Bx[(size_t)(n0 + row) * KTOT + (c + 1) * BK + q * 8];
            }
        }

        #pragma unroll
        for (int kk = 0; kk < 4; kk++) {
            uint32_t a[4][4], b[2][4];
            #pragma unroll
            for (int mt = 0; mt < 4; mt++) {
                int row = rA + mt * 16;
                ldsm4(a[mt], sA32 + row * 128 + ((kk * 32 + hbA) ^ ((row << 4) & 0x70)));
            }
            #pragma unroll
            for (int h = 0; h < 2; h++) {
                int row = rB + h * 16;
                ldsm4(b[h], sB32 + row * 128 + ((kk * 32 + hbB) ^ ((row << 4) & 0x70)));
            }
            #pragma unroll
            for (int mt = 0; mt < 4; mt++)
                #pragma unroll
                for (int nt = 0; nt < 4; nt++)
                    mma16816(acc[mt][nt], a[mt], b[nt >> 1][(nt & 1) * 2], b[nt >> 1][(nt & 1) * 2 + 1]);
        }
        __syncthreads();
    }

    const int er = lane >> 2;
    const int ec = (lane & 3) * 2;
    #pragma unroll
    for (int mt = 0; mt < 4; mt++) {
        int m = m0 + warp_m * 64 + mt * 16 + er;
        #pragma unroll
        for (int nt = 0; nt < 4; nt++) {
            int n = n0 + warp_n * 32 + nt * 8 + ec;
            float2 bias = *(const float2*)&g_bp[n];
            float2 o0 = make_float2(acc[mt][nt][0] + bias.x, acc[mt][nt][1] + bias.y);
            float2 o1 = make_float2(acc[mt][nt][2] + bias.x, acc[mt][nt][3] + bias.y);
            *(float2*)&g_xp[(size_t)m * NC + n]       = o0;
            *(float2*)&g_xp[(size_t)(m + 8) * NC + n] = o1;
        }
    }
}

// ============================ recurrent kernel: st.async + balanced stage2 ============================
// R14 structure with two changes:
//  (1) xp LDGs hoisted ABOVE the slot-A wait (DRAM latency hidden under the mbar wait)
//  (2) stage2-B moved to warps 4-7 (tid 128..255): warps 0-7 each own ONE stage2 per step.
__global__ void __cluster_dims__(CLUSTER, 1, 1) __launch_bounds__(RTHR, 1)
recur_kernel(float* __restrict__ out)
{
    extern __shared__ float sm[];
    float* hbA = sm;            // [2][1024]
    float* hbB = sm + 2048;     // [2][1024]
    float* pbA = sm + 4096;     // [8][4][128]
    float* pbB = sm + 8192;     // [8][4][128]
    unsigned long long* mb = (unsigned long long*)(sm + 12288);  // [g2][slot2]

    const int tid  = threadIdx.x;
    const int part = blockIdx.x & (CLUSTER - 1);
    const int grp  = blockIdx.x >> 3;
    const int kc   = tid >> 7;
    const int c    = tid & 127;

    const uint32_t mb32  = smem_u32(mb);
    const uint32_t hbA32 = smem_u32(hbA);
    const uint32_t hbB32 = smem_u32(hbB);

    float w[32];
    {
        const float* src = &g_Whp[(size_t)((part * 8 + kc) * 32) * 128 + c];
        #pragma unroll
        for (int i = 0; i < 32; i++) w[i] = src[(size_t)i * 128];
    }

    for (int i = tid; i < 4096; i += RTHR) sm[i] = 0.0f;
    if (tid == 0) {
        #pragma unroll
        for (int q = 0; q < 4; q++)
            asm volatile("mbarrier.init.shared.b64 [%0], %1;"
                         :: "r"(mb32 + q * 8), "r"(1u) : "memory");
        MBAR_EXPECT(mb32 + 0,  XBYTES);   // A slot 0 (ex 0)
        MBAR_EXPECT(mb32 + 8,  XBYTES);   // A slot 1 (ex 1)
        MBAR_EXPECT(mb32 + 16, XBYTES);   // B slot 0 (ex 0)
        MBAR_EXPECT(mb32 + 24, XBYTES);   // B slot 1 (ex 1)
    }
    __syncthreads();
    asm volatile("barrier.cluster.arrive.aligned;" ::: "memory");
    asm volatile("barrier.cluster.wait.aligned;" ::: "memory");

    // stage2 identities:
    //   A: warps 0-3  (tid 0..127):   cb = tid>>5,        batch bgA = grp*8 + cb
    //   B: warps 4-7  (tid 128..255): cb = (tid>>5) - 4,  batch bgB = grp*8 + 4 + cb
    const int wslot = tid >> 7;           // 0 => stage2A owner, 1 => stage2B owner, else none
    const int cb = (tid >> 5) & 3;
    const int cu = tid & 31;
    const int j  = part * 32 + cu;
    const int bgA = grp * 8 + cb;
    const int bgB = grp * 8 + 4 + cb;
    float cs = 0.0f;                      // csA in warps 0-3, csB in warps 4-7

    const size_t HT_OFF = (size_t)TSTEPS * BATCH * DHID;

    for (int t = 0; t < TSTEPS; t++) {
        const int p = t & 1;

        // hoisted xp prefetch for BOTH slots (no dependence on exchanges; hides DRAM under wait)
        float4 xp4;
        if (wslot == 0)
            xp4 = *(const float4*)&g_xp[((size_t)t * BATCH + bgA) * NC + part * 128 + cu * 4];
        else if (wslot == 1)
            xp4 = *(const float4*)&g_xp[((size_t)t * BATCH + bgB) * NC + part * 128 + cu * 4];

        // ======================= slot A =======================
        if (t > 0) {
            MBAR_WAIT(mb32 + (uint32_t)(((t - 1) & 1) * 8), (uint32_t)(((t - 1) >> 1) & 1));
            if (tid == 0) MBAR_EXPECT(mb32 + (uint32_t)(((t - 1) & 1) * 8), XBYTES);  // arm ex t+1
        }

        {   // stage 1 A (all 32 warps)
            unsigned long long acc01 = 0ull, acc23 = 0ull;
            const float* hrow = hbA + p * 1024 + kc * 128;
            #pragma unroll
            for (int i = 0; i < 32; i++) {
                ulonglong2 hh = *(const ulonglong2*)&hrow[i * 4];
                unsigned long long ww;
                asm("mov.b64 %0, {%1, %1};" : "=l"(ww) : "f"(w[i]));
                asm("fma.rn.f32x2 %0, %1, %2, %0;" : "+l"(acc01) : "l"(ww), "l"(hh.x));
                asm("fma.rn.f32x2 %0, %1, %2, %0;" : "+l"(acc23) : "l"(ww), "l"(hh.y));
            }
            float a0, a1, a2, a3;
            asm("mov.b64 {%0, %1}, %2;" : "=f"(a0), "=f"(a1) : "l"(acc01));
            asm("mov.b64 {%0, %1}, %2;" : "=f"(a2), "=f"(a3) : "l"(acc23));
            pbA[kc * 512 + 0 * 128 + c] = a0;
            pbA[kc * 512 + 1 * 128 + c] = a1;
            pbA[kc * 512 + 2 * 128 + c] = a2;
            pbA[kc * 512 + 3 * 128 + c] = a3;
        }
        __syncthreads();

        if (wslot == 0) {   // stage 2 A (warps 0-3)
            float4 s = make_float4(0.f, 0.f, 0.f, 0.f);
            #pragma unroll
            for (int q = 0; q < 8; q++) {
                float4 p4 = *(const float4*)&pbA[q * 512 + cb * 128 + cu * 4];
                s.x += p4.x; s.y += p4.y; s.z += p4.z; s.w += p4.w;
            }
            float fv = 1.0f / (1.0f + __expf(-(s.x + xp4.x)));
            float iv = 1.0f / (1.0f + __expf(-(s.y + xp4.y)));
            float ov = 1.0f / (1.0f + __expf(-(s.w + xp4.w)));
            float gt, ht;
            asm("tanh.approx.f32 %0, %1;" : "=f"(gt) : "f"(s.z + xp4.z));
            cs = fv * cs + iv * gt;
            asm("tanh.approx.f32 %0, %1;" : "=f"(ht) : "f"(cs));
            float h = ov * ht;

            if (t < TSTEPS - 1) {
                unsigned dst = hbA32 + (unsigned)(((1 - p) * 1024 + j * 4 + cb) * 4);
                unsigned mba = mb32 + (unsigned)(p * 8);
                #pragma unroll
                for (int r = 0; r < CLUSTER; r++)
                    st_async_f32(dst, mba, (unsigned)r, h);
            }

            out[(size_t)t * (BATCH * DHID) + (size_t)bgA * DHID + j] = h;
            if (t == TSTEPS - 1) {
                out[HT_OFF + (size_t)bgA * DHID + j] = h;
                out[HT_OFF + (size_t)BATCH * DHID + (size_t)bgA * DHID + j] = cs;
            }
        }

        // ======================= slot B =======================
        if (t > 0) {
            MBAR_WAIT(mb32 + 16u + (uint32_t)(((t - 1) & 1) * 8), (uint32_t)(((t - 1) >> 1) & 1));
            if (tid == 0) MBAR_EXPECT(mb32 + 16u + (uint32_t)(((t - 1) & 1) * 8), XBYTES);
        }

        {   // stage 1 B (all 32 warps)
            unsigned long long acc01 = 0ull, acc23 = 0ull;
            const float* hrow = hbB + p * 1024 + kc * 128;
            #pragma unroll
            for (int i = 0; i < 32; i++) {
                ulonglong2 hh = *(const ulonglong2*)&hrow[i * 4];
                unsigned long long ww;
                asm("mov.b64 %0, {%1, %1};" : "=l"(ww) : "f"(w[i]));
                asm("fma.rn.f32x2 %0, %1, %2, %0;" : "+l"(acc01) : "l"(ww), "l"(hh.x));
                asm("fma.rn.f32x2 %0, %1, %2, %0;" : "+l"(acc23) : "l"(ww), "l"(hh.y));
            }
            float a0, a1, a2, a3;
            asm("mov.b64 {%0, %1}, %2;" : "=f"(a0), "=f"(a1) : "l"(acc01));
            asm("mov.b64 {%0, %1}, %2;" : "=f"(a2), "=f"(a3) : "l"(acc23));
            pbB[kc * 512 + 0 * 128 + c] = a0;
            pbB[kc * 512 + 1 * 128 + c] = a1;
            pbB[kc * 512 + 2 * 128 + c] = a2;
            pbB[kc * 512 + 3 * 128 + c] = a3;
        }
        __syncthreads();

        if (wslot == 1) {   // stage 2 B (warps 4-7)
            float4 s = make_float4(0.f, 0.f, 0.f, 0.f);
            #pragma unroll
            for (int q = 0; q < 8; q++) {
                float4 p4 = *(const float4*)&pbB[q * 512 + cb * 128 + cu * 4];
                s.x += p4.x; s.y += p4.y; s.z += p4.z; s.w += p4.w;
            }
            float fv = 1.0f / (1.0f + __expf(-(s.x + xp4.x)));
            float iv = 1.0f / (1.0f + __expf(-(s.y + xp4.y)));
            float ov = 1.0f / (1.0f + __expf(-(s.w + xp4.w)));
            float gt, ht;
            asm("tanh.approx.f32 %0, %1;" : "=f"(gt) : "f"(s.z + xp4.z));
            cs = fv * cs + iv * gt;
            asm("tanh.approx.f32 %0, %1;" : "=f"(ht) : "f"(cs));
            float h = ov * ht;

            if (t < TSTEPS - 1) {
                unsigned dst = hbB32 + (unsigned)(((1 - p) * 1024 + j * 4 + cb) * 4);
                unsigned mba = mb32 + 16u + (unsigned)(p * 8);
                #pragma unroll
                for (int r = 0; r < CLUSTER; r++)
                    st_async_f32(dst, mba, (unsigned)r, h);
            }

            out[(size_t)t * (BATCH * DHID) + (size_t)bgB * DHID + j] = h;
            if (t == TSTEPS - 1) {
                out[HT_OFF + (size_t)bgB * DHID + j] = h;
                out[HT_OFF + (size_t)BATCH * DHID + (size_t)bgB * DHID + j] = cs;
            }
        }
    }

    // exit barrier: all CTAs alive until every peer is past its last wait
    asm volatile("barrier.cluster.arrive.aligned;" ::: "memory");
    asm volatile("barrier.cluster.wait.aligned;" ::: "memory");
}

// ============================ launch ============================
#define RSMEM (12288 * 4 + 64)

extern "C" void kernel_launch(void* const* d_in, const int* in_sizes, int n_in,
                              void* d_out, int out_size)
{
    const float* X  = (const float*)d_in[0];
    const float* Wf = (const float*)d_in[1];
    const float* bf = (const float*)d_in[2];
    const float* Wi = (const float*)d_in[3];
    const float* bi = (const float*)d_in[4];
    const float* Wg = (const float*)d_in[5];
    const float* bg = (const float*)d_in[6];
    const float* Wo = (const float*)d_in[7];
    const float* bo = (const float*)d_in[8];
    float* out = (float*)d_out;

    cudaFuncSetAttribute(recur_kernel, cudaFuncAttributeMaxDynamicSharedMemorySize, RSMEM);

    packB_kernel<<<(DIN * NC + 255) / 256, 256>>>(Wf, bf, Wi, bi, Wg, bg, Wo, bo);
    packA_kernel<<<(M_TOTAL * (DIN / 4) + 255) / 256, 256>>>(X);

    dim3 ggrid(NC / 128, M_TOTAL / 128);
    xproj_mma<<<ggrid, XT>>>();

    recur_kernel<<<NCTA, RTHR, RSMEM>>>(out);
}